// round 15
// baseline (speedup 1.0000x reference)
#include <cuda_runtime.h>
#include <cuda_fp16.h>
#include <cstdint>
#include <math.h>

// ---------------------------------------------------------------------------
// Problem constants
// ---------------------------------------------------------------------------
#define BATCH  32
#define SEQ    480
#define DIMN   1024
#define HEADS  16
#define HD     64
#define MROWS  (BATCH * SEQ)        // 15360
#define PLD    3072                 // fused QKV projection row stride
#define LOG2E  1.4426950408889634f
#define SCALE_LOG2E (0.125f * LOG2E)

// ---------------------------------------------------------------------------
// Device scratch (allocation-free)
// ---------------------------------------------------------------------------
__device__ __half g_QKVhi[(size_t)MROWS * PLD];
__device__ __half g_qhi[(size_t)MROWS * DIMN];
__device__ __half g_Ohi[(size_t)MROWS * DIMN];
__device__ __half g_Wcat_hi[(size_t)PLD * DIMN];  // [Wq;Wk;Wv]
__device__ __half g_Wo_hi[(size_t)DIMN * DIMN];
__device__ float  g_pe2[(size_t)SEQ * SEQ];       // pe * log2e

// ---------------------------------------------------------------------------
// PTX helpers (sm_80-era, arch-portable: mma.sync / ldmatrix / cp.async)
// ---------------------------------------------------------------------------
__device__ __forceinline__ uint32_t smem_to_u32(const void* p) {
    uint32_t a;
    asm("{ .reg .u64 t; cvta.to.shared.u64 t, %1; cvt.u32.u64 %0, t; }"
        : "=r"(a) : "l"(p));
    return a;
}

__device__ __forceinline__ void mma16816(float* d, const uint32_t* a,
                                         const uint32_t* b) {
    asm volatile(
        "mma.sync.aligned.m16n8k16.row.col.f32.f16.f16.f32 "
        "{%0,%1,%2,%3}, {%4,%5,%6,%7}, {%8,%9}, {%0,%1,%2,%3};"
        : "+f"(d[0]), "+f"(d[1]), "+f"(d[2]), "+f"(d[3])
        : "r"(a[0]), "r"(a[1]), "r"(a[2]), "r"(a[3]),
          "r"(b[0]), "r"(b[1]));
}

__device__ __forceinline__ void ldsm_x4(uint32_t* r, uint32_t saddr) {
    asm volatile(
        "ldmatrix.sync.aligned.m8n8.x4.shared.b16 {%0,%1,%2,%3}, [%4];"
        : "=r"(r[0]), "=r"(r[1]), "=r"(r[2]), "=r"(r[3]) : "r"(saddr));
}

__device__ __forceinline__ void ldsm_x4_t(uint32_t* r, uint32_t saddr) {
    asm volatile(
        "ldmatrix.sync.aligned.m8n8.x4.trans.shared.b16 {%0,%1,%2,%3}, [%4];"
        : "=r"(r[0]), "=r"(r[1]), "=r"(r[2]), "=r"(r[3]) : "r"(saddr));
}

__device__ __forceinline__ void cp16(uint32_t s, const void* g) {
    asm volatile("cp.async.cg.shared.global [%0], [%1], 16;"
                 :: "r"(s), "l"(g));
}
#define CP_COMMIT() asm volatile("cp.async.commit_group;" ::: "memory")
#define CP_WAIT1()  asm volatile("cp.async.wait_group 1;"  ::: "memory")

__device__ __forceinline__ uint32_t pack_h2(float a, float b) {
    __half2 h = __half2{__float2half_rn(a), __float2half_rn(b)};
    return *(uint32_t*)&h;
}

// 128B-row swizzle (rows of 64 halves): chunk c in 0..7
__device__ __forceinline__ uint32_t sw128(int row, int chunk) {
    return (uint32_t)(row * 128 + ((chunk ^ (row & 7)) << 4));
}

// ---------------------------------------------------------------------------
// Unified prep kernel: q tohalf + 4 weight tohalf + pe*log2e, one launch.
// ---------------------------------------------------------------------------
#define PREP_QBLKS (MROWS * DIMN / 1024)          // 15360
#define PREP_WBLKS 1024
#define PREP_PEBLKS (SEQ * SEQ / 1024)            // 225
#define PREP_TOTAL (PREP_QBLKS + 4 * PREP_WBLKS + PREP_PEBLKS)   // 19681

__global__ __launch_bounds__(256)
void prep_kernel(const float* __restrict__ q,
                 const float* __restrict__ w0, const float* __restrict__ w1,
                 const float* __restrict__ w2, const float* __restrict__ w3,
                 const float* __restrict__ pe,
                 __half* __restrict__ qh,
                 __half* __restrict__ h0, __half* __restrict__ h1,
                 __half* __restrict__ h2, __half* __restrict__ h3,
                 float* __restrict__ pe2)
{
    const int blk = blockIdx.x;
    if (blk < PREP_QBLKS + 4 * PREP_WBLKS) {
        const float* x;
        __half* y;
        int i;
        if (blk < PREP_QBLKS) {
            x = q; y = qh;
            i = (blk * 256 + (int)threadIdx.x) * 4;
        } else {
            const int wb = blk - PREP_QBLKS;
            const int seg = wb >> 10;
            x = (seg == 0) ? w0 : (seg == 1) ? w1 : (seg == 2) ? w2 : w3;
            y = (seg == 0) ? h0 : (seg == 1) ? h1 : (seg == 2) ? h2 : h3;
            i = ((wb & 1023) * 256 + (int)threadIdx.x) * 4;
        }
        float4 v = *(const float4*)(x + i);
        __half2* hp = (__half2*)(y + i);
        hp[0] = __half2{__float2half_rn(v.x), __float2half_rn(v.y)};
        hp[1] = __half2{__float2half_rn(v.z), __float2half_rn(v.w)};
    } else {
        const int pb = blk - PREP_QBLKS - 4 * PREP_WBLKS;
        const int i = (pb * 256 + (int)threadIdx.x) * 4;
        float4 v = *(const float4*)(pe + i);
        v.x *= LOG2E; v.y *= LOG2E; v.z *= LOG2E; v.w *= LOG2E;
        *(float4*)(pe2 + i) = v;
    }
}

// ---------------------------------------------------------------------------
// fp16 x1 tensor-core GEMM: C = Ah @ Bh^T (+bias).  [Round-14 config]
// CTA tile 128x128, 128 threads = 4 warps of 64x64 (2x2), BK=64,
// 3-stage cp.async ring, ONE sync per stage, sw128 swizzle, 2 CTAs/SM.
// ---------------------------------------------------------------------------
#define TILE_B (128 * 128)               // 16384 = 128 rows x 128B
#define OFF_A  0
#define OFF_B  TILE_B
#define BUF_B  (2 * TILE_B)              // 32768 per stage
#define GEMM_SMEM (3 * BUF_B)            // 98304
#define GTHREADS 128

template <bool BIAS, bool HOUT>
__global__ __launch_bounds__(GTHREADS, 2)
void gemm_f16x1(const __half* __restrict__ Ahi,
                const __half* __restrict__ Bhi,
                const float* __restrict__ bias,
                float* __restrict__ C,
                __half* __restrict__ Chi, int ldc)
{
    extern __shared__ __align__(128) char smem[];
    const uint32_t sb = smem_to_u32(smem);

    const int tid  = threadIdx.x;
    const int lane = tid & 31;
    const int wid  = tid >> 5;           // 0..3
    const int wm   = wid >> 1;           // 0..1 -> 64-row slice
    const int wn   = wid & 1;            // 0..1 -> 64-col slice
    const int m0   = blockIdx.y * 128;
    const int n0   = blockIdx.x * 128;

    const int wrow = tid >> 3;           // 0..15 (+16 per round)
    const int wch  = tid & 7;
    const __half* gA = Ahi + (size_t)(m0 + wrow) * DIMN + wch * 8;
    const __half* gB = Bhi + (size_t)(n0 + wrow) * DIMN + wch * 8;
    uint32_t wsw[8];
#pragma unroll
    for (int i = 0; i < 8; i++) wsw[i] = sw128(wrow + 16 * i, wch);

    const int Ra   = wm * 64 + (lane & 15);
    const int xorA = Ra & 7;
    const int ca   = lane >> 4;                     // + 2*kk
    const uint32_t aBase = (uint32_t)(Ra * 128);
    const int Rb   = wn * 64 + ((lane >> 4) << 3) + (lane & 7);
    const int xorB = Rb & 7;
    const int cb   = (lane >> 3) & 1;               // + 2*kk
    const uint32_t bBase = (uint32_t)(Rb * 128);

    float acc[4][8][4];
#pragma unroll
    for (int i = 0; i < 4; i++)
#pragma unroll
        for (int j = 0; j < 8; j++)
#pragma unroll
            for (int c = 0; c < 4; c++) acc[i][j][c] = 0.f;

    auto issue_loads = [&](int s) {
        const int k0 = s * 64;
        const uint32_t base = sb + (uint32_t)((s % 3) * BUF_B);
#pragma unroll
        for (int i = 0; i < 8; i++) {
            cp16(base + OFF_A + wsw[i], gA + (size_t)(16 * i) * DIMN + k0);
            cp16(base + OFF_B + wsw[i], gB + (size_t)(16 * i) * DIMN + k0);
        }
    };

    issue_loads(0); CP_COMMIT();
    issue_loads(1); CP_COMMIT();

    uint32_t ah[2][4][4], bh[2][4][4];

    for (int s = 0; s < 16; s++) {
        CP_WAIT1();
        __syncthreads();                 // stage s ready; buf (s+2)%3 free

        if (s + 2 < 16) issue_loads(s + 2);
        CP_COMMIT();

        const uint32_t base = sb + (uint32_t)((s % 3) * BUF_B);

#pragma unroll
        for (int mi = 0; mi < 4; mi++)
            ldsm_x4(ah[0][mi], base + OFF_A + aBase + mi * 2048 +
                               (uint32_t)((ca ^ xorA) << 4));
#pragma unroll
        for (int bn = 0; bn < 4; bn++)
            ldsm_x4(bh[0][bn], base + OFF_B + bBase + bn * 2048 +
                               (uint32_t)((cb ^ xorB) << 4));

#pragma unroll
        for (int kk = 0; kk < 4; kk++) {
            const int cur = kk & 1, nxt = cur ^ 1;
            if (kk < 3) {
#pragma unroll
                for (int mi = 0; mi < 4; mi++)
                    ldsm_x4(ah[nxt][mi], base + OFF_A + aBase + mi * 2048 +
                                         (uint32_t)(((ca + 2 * (kk + 1)) ^ xorA) << 4));
#pragma unroll
                for (int bn = 0; bn < 4; bn++)
                    ldsm_x4(bh[nxt][bn], base + OFF_B + bBase + bn * 2048 +
                                         (uint32_t)(((cb + 2 * (kk + 1)) ^ xorB) << 4));
            }
#pragma unroll
            for (int mi = 0; mi < 4; mi++)
#pragma unroll
                for (int ni = 0; ni < 8; ni++)
                    mma16816(acc[mi][ni], ah[cur][mi], &bh[cur][ni >> 1][(ni & 1) * 2]);
        }
    }

#pragma unroll
    for (int mi = 0; mi < 4; mi++) {
        const int row = m0 + wm * 64 + mi * 16 + (lane >> 2);
#pragma unroll
        for (int ni = 0; ni < 8; ni++) {
            const int col = n0 + wn * 64 + ni * 8 + ((lane & 3) << 1);
            if (HOUT) {
                *(__half2*)(Chi + (size_t)row * ldc + col) =
                    __half2{__float2half_rn(acc[mi][ni][0]),
                            __float2half_rn(acc[mi][ni][1])};
                *(__half2*)(Chi + (size_t)(row + 8) * ldc + col) =
                    __half2{__float2half_rn(acc[mi][ni][2]),
                            __float2half_rn(acc[mi][ni][3])};
            } else {
                float b0 = 0.f, b1 = 0.f;
                if (BIAS) { b0 = bias[col]; b1 = bias[col + 1]; }
                float2 v0 = make_float2(acc[mi][ni][0] + b0, acc[mi][ni][1] + b1);
                float2 v1 = make_float2(acc[mi][ni][2] + b0, acc[mi][ni][3] + b1);
                *(float2*)(C + (size_t)row * ldc + col)       = v0;
                *(float2*)(C + (size_t)(row + 8) * ldc + col) = v1;
            }
        }
    }
}

// ---------------------------------------------------------------------------
// Tensor-core flash attention (all x1), v2:
// 96 threads = 3 warps, each owning 32 q-rows (2 m-fragments). grid (5, B*H).
// K/V fragments loaded 3x instead of 6x -> smem-read traffic nearly halved.
// 3-stage KV ring (Khi,Vhi), ONE sync per block, 128B-row swizzle, exp2f.
// ---------------------------------------------------------------------------
#define QROWS 96
#define ATHREADS 96
#define KV_PLANE (64 * 128)              // 8192
#define KV_STAGE (2 * KV_PLANE)          // 16384
#define Q_OFF (3 * KV_STAGE)             // 49152
#define ATTN_SMEM (Q_OFF + QROWS * 128)  // 61440

__global__ __launch_bounds__(ATHREADS, 2)
void attn_mma_kernel(const float* __restrict__ pe2,
                     const __half* __restrict__ QKVhi,
                     __half* __restrict__ Ohi)
{
    extern __shared__ __align__(128) char smem[];
    const uint32_t sb = smem_to_u32(smem);
    const int tid  = threadIdx.x;
    const int lane = tid & 31;
    const int wid  = tid >> 5;           // 0..2
    const int q0   = blockIdx.x * QROWS;
    const int bh   = blockIdx.y;
    const int b    = bh >> 4;
    const int h    = bh & 15;

    const size_t rowbase = (size_t)b * SEQ;

    auto load_kv = [&](int kb) {
        const int k0 = kb * 64;
        const uint32_t stg = sb + (uint32_t)((kb % 3) * KV_STAGE);
        for (int c = tid; c < 1024; c += ATHREADS) {
            const int plane = c >> 9;           // 0 Khi 1 Vhi
            const int idx = c & 511;
            const int row = idx >> 3, ch = idx & 7;
            int kr = k0 + row;
            if (kr >= SEQ) kr = SEQ - 1;        // clamp; masked via S later
            const int coloff = (plane == 0) ? DIMN : 2 * DIMN;
            cp16(stg + plane * KV_PLANE + sw128(row, ch),
                 QKVhi + (rowbase + kr) * PLD + coloff + h * HD + ch * 8);
        }
    };

    {
        const size_t gq = (rowbase + q0) * PLD + h * HD;
        for (int c = tid; c < QROWS * 8; c += ATHREADS) {
            const int row = c >> 3, ch = c & 7;
            cp16(sb + Q_OFF + sw128(row, ch), QKVhi + gq + (size_t)row * PLD + ch * 8);
        }
    }
    load_kv(0); CP_COMMIT();
    load_kv(1); CP_COMMIT();

    // reader mappings
    const int Rq   = wid * 32 + (lane & 15);    // + mi*16 (xor invariant)
    const int xorQ = Rq & 7;
    const int cqa  = lane >> 4;                 // + 2*ks
    const uint32_t qBase = sb + Q_OFF + (uint32_t)(Rq * 128);
    const int Rk   = ((lane >> 4) << 3) + (lane & 7);
    const int xorK = lane & 7;
    const int ckb  = (lane >> 3) & 1;
    const int Rv   = lane & 15;
    const int xorV = lane & 7;
    const int cvb  = lane >> 4;

    const int r0  = lane >> 2;
    const int c2  = (lane & 3) * 2;
    // global q rows for mi=0,1: qrm[mi] and qrm[mi]+8
    const int qrm0 = q0 + wid * 32 + r0;
    const int qrm1 = qrm0 + 16;

    float o[2][8][4];
#pragma unroll
    for (int m = 0; m < 2; m++)
#pragma unroll
        for (int i = 0; i < 8; i++)
#pragma unroll
            for (int c = 0; c < 4; c++) o[m][i][c] = 0.f;
    float mrow0[2] = {-INFINITY, -INFINITY};
    float mrow1[2] = {-INFINITY, -INFINITY};
    float lsum0[2] = {0.f, 0.f};
    float lsum1[2] = {0.f, 0.f};

    for (int kb = 0; kb < 8; kb++) {
        CP_WAIT1();
        __syncthreads();

        if (kb + 2 < 8) load_kv(kb + 2);
        CP_COMMIT();

        const uint32_t kvbase = sb + (uint32_t)((kb % 3) * KV_STAGE);
        const int k0 = kb * 64;

        // ---- S = Qh @ Kh^T (both m-fragments share the K fragments) ----
        float s[2][8][4];
#pragma unroll
        for (int m = 0; m < 2; m++)
#pragma unroll
            for (int i = 0; i < 8; i++)
#pragma unroll
                for (int c = 0; c < 4; c++) s[m][i][c] = 0.f;

#pragma unroll
        for (int ks = 0; ks < 4; ks++) {
            uint32_t qh[2][4];
#pragma unroll
            for (int m = 0; m < 2; m++)
                ldsm_x4(qh[m], qBase + (uint32_t)(m * 16 * 128) +
                               (uint32_t)((((cqa + 2 * ks) ^ xorQ)) << 4));
            uint32_t kh[4][4];
#pragma unroll
            for (int ng = 0; ng < 4; ng++)
                ldsm_x4(kh[ng], kvbase + (uint32_t)((Rk + ng * 16) * 128) +
                                (uint32_t)((((ckb + 2 * ks) ^ xorK)) << 4));
#pragma unroll
            for (int m = 0; m < 2; m++)
#pragma unroll
                for (int ni = 0; ni < 8; ni++)
                    mma16816(s[m][ni], qh[m], &kh[ni >> 1][(ni & 1) * 2]);
        }

        // ---- scale + pe bias + mask + online softmax per m-fragment ----
        uint32_t phi[2][4][4];
#pragma unroll
        for (int m = 0; m < 2; m++) {
            const int qr = (m == 0) ? qrm0 : qrm1;
            const float* peA = pe2 + (size_t)qr * SEQ;
            const float* peB = pe2 + (size_t)(qr + 8) * SEQ;
#pragma unroll
            for (int ni = 0; ni < 8; ni++) {
                const int kc = k0 + ni * 8 + c2;
                if (kc < SEQ) {
                    float2 pA = *(const float2*)(peA + kc);
                    float2 pB = *(const float2*)(peB + kc);
                    s[m][ni][0] = s[m][ni][0] * SCALE_LOG2E + pA.x;
                    s[m][ni][1] = s[m][ni][1] * SCALE_LOG2E + pA.y;
                    s[m][ni][2] = s[m][ni][2] * SCALE_LOG2E + pB.x;
                    s[m][ni][3] = s[m][ni][3] * SCALE_LOG2E + pB.y;
                } else {
                    s[m][ni][0] = -1e30f; s[m][ni][1] = -1e30f;
                    s[m][ni][2] = -1e30f; s[m][ni][3] = -1e30f;
                }
            }

            float m0 = -INFINITY, m1 = -INFINITY;
#pragma unroll
            for (int ni = 0; ni < 8; ni++) {
                m0 = fmaxf(m0, fmaxf(s[m][ni][0], s[m][ni][1]));
                m1 = fmaxf(m1, fmaxf(s[m][ni][2], s[m][ni][3]));
            }
            m0 = fmaxf(m0, __shfl_xor_sync(0xffffffffu, m0, 1));
            m0 = fmaxf(m0, __shfl_xor_sync(0xffffffffu, m0, 2));
            m1 = fmaxf(m1, __shfl_xor_sync(0xffffffffu, m1, 1));
            m1 = fmaxf(m1, __shfl_xor_sync(0xffffffffu, m1, 2));

            const float mn0 = fmaxf(mrow0[m], m0);
            const float mn1 = fmaxf(mrow1[m], m1);
            const float f0 = exp2f(mrow0[m] - mn0);
            const float f1 = exp2f(mrow1[m] - mn1);
            mrow0[m] = mn0; mrow1[m] = mn1;

            float sum0 = 0.f, sum1 = 0.f;
#pragma unroll
            for (int ks = 0; ks < 4; ks++) {
                const int n0i = 2 * ks, n1i = 2 * ks + 1;
                float p00 = exp2f(s[m][n0i][0] - mn0), p01 = exp2f(s[m][n0i][1] - mn0);
                float p02 = exp2f(s[m][n0i][2] - mn1), p03 = exp2f(s[m][n0i][3] - mn1);
                float p10 = exp2f(s[m][n1i][0] - mn0), p11 = exp2f(s[m][n1i][1] - mn0);
                float p12 = exp2f(s[m][n1i][2] - mn1), p13 = exp2f(s[m][n1i][3] - mn1);
                sum0 += p00 + p01 + p10 + p11;
                sum1 += p02 + p03 + p12 + p13;
                phi[m][ks][0] = pack_h2(p00, p01);
                phi[m][ks][1] = pack_h2(p02, p03);
                phi[m][ks][2] = pack_h2(p10, p11);
                phi[m][ks][3] = pack_h2(p12, p13);
            }
            lsum0[m] = lsum0[m] * f0 + sum0;
            lsum1[m] = lsum1[m] * f1 + sum1;

#pragma unroll
            for (int ni = 0; ni < 8; ni++) {
                o[m][ni][0] *= f0; o[m][ni][1] *= f0;
                o[m][ni][2] *= f1; o[m][ni][3] *= f1;
            }
        }

        // ---- O += Ph @ Vh (both m-fragments share the V fragments) ----
#pragma unroll
        for (int ks = 0; ks < 4; ks++) {
            uint32_t vh[4][4];
#pragma unroll
            for (int dg = 0; dg < 4; dg++)
                ldsm_x4_t(vh[dg], kvbase + KV_PLANE +
                                  (uint32_t)((Rv + ks * 16) * 128) +
                                  (uint32_t)((((cvb + 2 * dg) ^ xorV)) << 4));
#pragma unroll
            for (int m = 0; m < 2; m++)
#pragma unroll
                for (int ni = 0; ni < 8; ni++)
                    mma16816(o[m][ni], phi[m][ks], &vh[ni >> 1][(ni & 1) * 2]);
        }
    }

    // ---- finalize ----
#pragma unroll
    for (int m = 0; m < 2; m++) {
        float l0 = lsum0[m], l1 = lsum1[m];
        l0 += __shfl_xor_sync(0xffffffffu, l0, 1);
        l0 += __shfl_xor_sync(0xffffffffu, l0, 2);
        l1 += __shfl_xor_sync(0xffffffffu, l1, 1);
        l1 += __shfl_xor_sync(0xffffffffu, l1, 2);
        const float inv0 = 1.f / l0;
        const float inv1 = 1.f / l1;

        const int qr = (m == 0) ? qrm0 : qrm1;
        const size_t orow0 = (rowbase + qr) * DIMN + h * HD;
        const size_t orow1 = (rowbase + qr + 8) * DIMN + h * HD;
#pragma unroll
        for (int ni = 0; ni < 8; ni++) {
            const int d = ni * 8 + c2;
            *(__half2*)(Ohi + orow0 + d) =
                __half2{__float2half_rn(o[m][ni][0] * inv0),
                        __float2half_rn(o[m][ni][1] * inv0)};
            *(__half2*)(Ohi + orow1 + d) =
                __half2{__float2half_rn(o[m][ni][2] * inv1),
                        __float2half_rn(o[m][ni][3] * inv1)};
        }
    }
}

// ---------------------------------------------------------------------------
extern "C" void kernel_launch(void* const* d_in, const int* in_sizes, int n_in,
                              void* d_out, int out_size)
{
    const float* q  = (const float*)d_in[0];
    const float* Wq = (const float*)d_in[1];
    const float* Wk = (const float*)d_in[2];
    const float* Wv = (const float*)d_in[3];
    const float* pe = (const float*)d_in[4];
    const float* Wo = (const float*)d_in[5];
    const float* bo = (const float*)d_in[6];
    float* out = (float*)d_out;

    __half *QKVhi, *qhi, *Ohi, *Wch, *Woh;
    float* pe2;
    cudaGetSymbolAddress((void**)&QKVhi, g_QKVhi);
    cudaGetSymbolAddress((void**)&qhi, g_qhi);
    cudaGetSymbolAddress((void**)&Ohi, g_Ohi);
    cudaGetSymbolAddress((void**)&Wch, g_Wcat_hi);
    cudaGetSymbolAddress((void**)&Woh, g_Wo_hi);
    cudaGetSymbolAddress((void**)&pe2, g_pe2);

    const int nw = DIMN * DIMN;

    // One launch: q tohalf + Wq/Wk/Wv/Wo tohalf + pe*log2e
    prep_kernel<<<PREP_TOTAL, 256>>>(q, Wq, Wk, Wv, Wo, pe,
                                     qhi, Wch, Wch + nw, Wch + 2 * nw, Woh, pe2);

    cudaFuncSetAttribute(gemm_f16x1<false, true>,
                         cudaFuncAttributeMaxDynamicSharedMemorySize, GEMM_SMEM);
    cudaFuncSetAttribute(gemm_f16x1<true, false>,
                         cudaFuncAttributeMaxDynamicSharedMemorySize, GEMM_SMEM);
    cudaFuncSetAttribute(attn_mma_kernel,
                         cudaFuncAttributeMaxDynamicSharedMemorySize, ATTN_SMEM);

    // Fused QKV projection -> fp16 hi [15360, 3072]
    gemm_f16x1<false, true><<<dim3(PLD / 128, MROWS / 128), GTHREADS, GEMM_SMEM>>>(
        qhi, Wch, nullptr, nullptr, QKVhi, PLD);

    // Tensor-core flash attention -> fp16 hi O
    attn_mma_kernel<<<dim3(SEQ / QROWS, BATCH * HEADS), ATHREADS, ATTN_SMEM>>>(
        pe2, QKVhi, Ohi);

    // Output projection + bias -> fp32 out
    gemm_f16x1<true, false><<<dim3(DIMN / 128, MROWS / 128), GTHREADS, GEMM_SMEM>>>(
        Ohi, Woh, bo, out, nullptr, DIMN);
}

// round 16
// speedup vs baseline: 1.1111x; 1.1111x over previous
#include <cuda_runtime.h>
#include <cuda_fp16.h>
#include <cstdint>
#include <math.h>

// ---------------------------------------------------------------------------
// Problem constants
// ---------------------------------------------------------------------------
#define BATCH  32
#define SEQ    480
#define DIMN   1024
#define HEADS  16
#define HD     64
#define MROWS  (BATCH * SEQ)        // 15360
#define PLD    3072                 // fused QKV projection row stride
#define LOG2E  1.4426950408889634f
#define SCALE_LOG2E (0.125f * LOG2E)

// ---------------------------------------------------------------------------
// Device scratch (allocation-free)
// ---------------------------------------------------------------------------
__device__ __half g_QKVhi[(size_t)MROWS * PLD];
__device__ __half g_qhi[(size_t)MROWS * DIMN];
__device__ __half g_Ohi[(size_t)MROWS * DIMN];
__device__ __half g_Wcat_hi[(size_t)PLD * DIMN];  // [Wq;Wk;Wv]
__device__ __half g_Wo_hi[(size_t)DIMN * DIMN];
__device__ float  g_pe2[(size_t)SEQ * SEQ];       // pe * log2e

// ---------------------------------------------------------------------------
// PTX helpers (sm_80-era, arch-portable: mma.sync / ldmatrix / cp.async)
// ---------------------------------------------------------------------------
__device__ __forceinline__ uint32_t smem_to_u32(const void* p) {
    uint32_t a;
    asm("{ .reg .u64 t; cvta.to.shared.u64 t, %1; cvt.u32.u64 %0, t; }"
        : "=r"(a) : "l"(p));
    return a;
}

__device__ __forceinline__ void mma16816(float* d, const uint32_t* a,
                                         const uint32_t* b) {
    asm volatile(
        "mma.sync.aligned.m16n8k16.row.col.f32.f16.f16.f32 "
        "{%0,%1,%2,%3}, {%4,%5,%6,%7}, {%8,%9}, {%0,%1,%2,%3};"
        : "+f"(d[0]), "+f"(d[1]), "+f"(d[2]), "+f"(d[3])
        : "r"(a[0]), "r"(a[1]), "r"(a[2]), "r"(a[3]),
          "r"(b[0]), "r"(b[1]));
}

__device__ __forceinline__ void ldsm_x4(uint32_t* r, uint32_t saddr) {
    asm volatile(
        "ldmatrix.sync.aligned.m8n8.x4.shared.b16 {%0,%1,%2,%3}, [%4];"
        : "=r"(r[0]), "=r"(r[1]), "=r"(r[2]), "=r"(r[3]) : "r"(saddr));
}

__device__ __forceinline__ void ldsm_x4_t(uint32_t* r, uint32_t saddr) {
    asm volatile(
        "ldmatrix.sync.aligned.m8n8.x4.trans.shared.b16 {%0,%1,%2,%3}, [%4];"
        : "=r"(r[0]), "=r"(r[1]), "=r"(r[2]), "=r"(r[3]) : "r"(saddr));
}

__device__ __forceinline__ void cp16(uint32_t s, const void* g) {
    asm volatile("cp.async.cg.shared.global [%0], [%1], 16;"
                 :: "r"(s), "l"(g));
}
#define CP_COMMIT() asm volatile("cp.async.commit_group;" ::: "memory")
#define CP_WAIT1()  asm volatile("cp.async.wait_group 1;"  ::: "memory")

__device__ __forceinline__ uint32_t pack_h2(float a, float b) {
    __half2 h = __half2{__float2half_rn(a), __float2half_rn(b)};
    return *(uint32_t*)&h;
}

// 128B-row swizzle (rows of 64 halves): chunk c in 0..7
__device__ __forceinline__ uint32_t sw128(int row, int chunk) {
    return (uint32_t)(row * 128 + ((chunk ^ (row & 7)) << 4));
}

// ---------------------------------------------------------------------------
// Unified prep kernel: q tohalf + 4 weight tohalf + pe*log2e, one launch.
// ---------------------------------------------------------------------------
#define PREP_QBLKS (MROWS * DIMN / 1024)          // 15360
#define PREP_WBLKS 1024
#define PREP_PEBLKS (SEQ * SEQ / 1024)            // 225
#define PREP_TOTAL (PREP_QBLKS + 4 * PREP_WBLKS + PREP_PEBLKS)   // 19681

__global__ __launch_bounds__(256)
void prep_kernel(const float* __restrict__ q,
                 const float* __restrict__ w0, const float* __restrict__ w1,
                 const float* __restrict__ w2, const float* __restrict__ w3,
                 const float* __restrict__ pe,
                 __half* __restrict__ qh,
                 __half* __restrict__ h0, __half* __restrict__ h1,
                 __half* __restrict__ h2, __half* __restrict__ h3,
                 float* __restrict__ pe2)
{
    const int blk = blockIdx.x;
    if (blk < PREP_QBLKS + 4 * PREP_WBLKS) {
        const float* x;
        __half* y;
        int i;
        if (blk < PREP_QBLKS) {
            x = q; y = qh;
            i = (blk * 256 + (int)threadIdx.x) * 4;
        } else {
            const int wb = blk - PREP_QBLKS;
            const int seg = wb >> 10;
            x = (seg == 0) ? w0 : (seg == 1) ? w1 : (seg == 2) ? w2 : w3;
            y = (seg == 0) ? h0 : (seg == 1) ? h1 : (seg == 2) ? h2 : h3;
            i = ((wb & 1023) * 256 + (int)threadIdx.x) * 4;
        }
        float4 v = *(const float4*)(x + i);
        __half2* hp = (__half2*)(y + i);
        hp[0] = __half2{__float2half_rn(v.x), __float2half_rn(v.y)};
        hp[1] = __half2{__float2half_rn(v.z), __float2half_rn(v.w)};
    } else {
        const int pb = blk - PREP_QBLKS - 4 * PREP_WBLKS;
        const int i = (pb * 256 + (int)threadIdx.x) * 4;
        float4 v = *(const float4*)(pe + i);
        v.x *= LOG2E; v.y *= LOG2E; v.z *= LOG2E; v.w *= LOG2E;
        *(float4*)(pe2 + i) = v;
    }
}

// ---------------------------------------------------------------------------
// fp16 x1 tensor-core GEMM: C = Ah @ Bh^T (+bias).  [Round-14 config]
// CTA tile 128x128, 128 threads = 4 warps of 64x64 (2x2), BK=64,
// 3-stage cp.async ring, ONE sync per stage, sw128 swizzle, 2 CTAs/SM.
// ---------------------------------------------------------------------------
#define TILE_B (128 * 128)               // 16384 = 128 rows x 128B
#define OFF_A  0
#define OFF_B  TILE_B
#define BUF_B  (2 * TILE_B)              // 32768 per stage
#define GEMM_SMEM (3 * BUF_B)            // 98304
#define GTHREADS 128

template <bool BIAS, bool HOUT>
__global__ __launch_bounds__(GTHREADS, 2)
void gemm_f16x1(const __half* __restrict__ Ahi,
                const __half* __restrict__ Bhi,
                const float* __restrict__ bias,
                float* __restrict__ C,
                __half* __restrict__ Chi, int ldc)
{
    extern __shared__ __align__(128) char smem[];
    const uint32_t sb = smem_to_u32(smem);

    const int tid  = threadIdx.x;
    const int lane = tid & 31;
    const int wid  = tid >> 5;           // 0..3
    const int wm   = wid >> 1;           // 0..1 -> 64-row slice
    const int wn   = wid & 1;            // 0..1 -> 64-col slice
    const int m0   = blockIdx.y * 128;
    const int n0   = blockIdx.x * 128;

    const int wrow = tid >> 3;           // 0..15 (+16 per round)
    const int wch  = tid & 7;
    const __half* gA = Ahi + (size_t)(m0 + wrow) * DIMN + wch * 8;
    const __half* gB = Bhi + (size_t)(n0 + wrow) * DIMN + wch * 8;
    uint32_t wsw[8];
#pragma unroll
    for (int i = 0; i < 8; i++) wsw[i] = sw128(wrow + 16 * i, wch);

    const int Ra   = wm * 64 + (lane & 15);
    const int xorA = Ra & 7;
    const int ca   = lane >> 4;                     // + 2*kk
    const uint32_t aBase = (uint32_t)(Ra * 128);
    const int Rb   = wn * 64 + ((lane >> 4) << 3) + (lane & 7);
    const int xorB = Rb & 7;
    const int cb   = (lane >> 3) & 1;               // + 2*kk
    const uint32_t bBase = (uint32_t)(Rb * 128);

    float acc[4][8][4];
#pragma unroll
    for (int i = 0; i < 4; i++)
#pragma unroll
        for (int j = 0; j < 8; j++)
#pragma unroll
            for (int c = 0; c < 4; c++) acc[i][j][c] = 0.f;

    auto issue_loads = [&](int s) {
        const int k0 = s * 64;
        const uint32_t base = sb + (uint32_t)((s % 3) * BUF_B);
#pragma unroll
        for (int i = 0; i < 8; i++) {
            cp16(base + OFF_A + wsw[i], gA + (size_t)(16 * i) * DIMN + k0);
            cp16(base + OFF_B + wsw[i], gB + (size_t)(16 * i) * DIMN + k0);
        }
    };

    issue_loads(0); CP_COMMIT();
    issue_loads(1); CP_COMMIT();

    uint32_t ah[2][4][4], bh[2][4][4];

    for (int s = 0; s < 16; s++) {
        CP_WAIT1();
        __syncthreads();                 // stage s ready; buf (s+2)%3 free

        if (s + 2 < 16) issue_loads(s + 2);
        CP_COMMIT();

        const uint32_t base = sb + (uint32_t)((s % 3) * BUF_B);

#pragma unroll
        for (int mi = 0; mi < 4; mi++)
            ldsm_x4(ah[0][mi], base + OFF_A + aBase + mi * 2048 +
                               (uint32_t)((ca ^ xorA) << 4));
#pragma unroll
        for (int bn = 0; bn < 4; bn++)
            ldsm_x4(bh[0][bn], base + OFF_B + bBase + bn * 2048 +
                               (uint32_t)((cb ^ xorB) << 4));

#pragma unroll
        for (int kk = 0; kk < 4; kk++) {
            const int cur = kk & 1, nxt = cur ^ 1;
            if (kk < 3) {
#pragma unroll
                for (int mi = 0; mi < 4; mi++)
                    ldsm_x4(ah[nxt][mi], base + OFF_A + aBase + mi * 2048 +
                                         (uint32_t)(((ca + 2 * (kk + 1)) ^ xorA) << 4));
#pragma unroll
                for (int bn = 0; bn < 4; bn++)
                    ldsm_x4(bh[nxt][bn], base + OFF_B + bBase + bn * 2048 +
                                         (uint32_t)(((cb + 2 * (kk + 1)) ^ xorB) << 4));
            }
#pragma unroll
            for (int mi = 0; mi < 4; mi++)
#pragma unroll
                for (int ni = 0; ni < 8; ni++)
                    mma16816(acc[mi][ni], ah[cur][mi], &bh[cur][ni >> 1][(ni & 1) * 2]);
        }
    }

#pragma unroll
    for (int mi = 0; mi < 4; mi++) {
        const int row = m0 + wm * 64 + mi * 16 + (lane >> 2);
#pragma unroll
        for (int ni = 0; ni < 8; ni++) {
            const int col = n0 + wn * 64 + ni * 8 + ((lane & 3) << 1);
            if (HOUT) {
                *(__half2*)(Chi + (size_t)row * ldc + col) =
                    __half2{__float2half_rn(acc[mi][ni][0]),
                            __float2half_rn(acc[mi][ni][1])};
                *(__half2*)(Chi + (size_t)(row + 8) * ldc + col) =
                    __half2{__float2half_rn(acc[mi][ni][2]),
                            __float2half_rn(acc[mi][ni][3])};
            } else {
                float b0 = 0.f, b1 = 0.f;
                if (BIAS) { b0 = bias[col]; b1 = bias[col + 1]; }
                float2 v0 = make_float2(acc[mi][ni][0] + b0, acc[mi][ni][1] + b1);
                float2 v1 = make_float2(acc[mi][ni][2] + b0, acc[mi][ni][3] + b1);
                *(float2*)(C + (size_t)row * ldc + col)       = v0;
                *(float2*)(C + (size_t)(row + 8) * ldc + col) = v1;
            }
        }
    }
}

// ---------------------------------------------------------------------------
// Tensor-core flash attention (all x1), v3:
// 192 threads (6 warps x 16 q-rows = 96 rows)  [R14 occupancy restored].
// Stages hold 128 keys (2 sub-blocks of 64 processed sequentially) ->
// HALF the barriers/loader rounds, identical per-64-key arithmetic.
// 3-stage ring (Khi,Vhi), 128B-row swizzle, exp2f softmax.
// ---------------------------------------------------------------------------
#define QROWS 96
#define ATHREADS 192
#define KV_PLANE (128 * 128)             // 16384 per plane (128 keys)
#define KV_STAGE (2 * KV_PLANE)          // 32768
#define Q_OFF (3 * KV_STAGE)             // 98304
#define ATTN_SMEM (Q_OFF + QROWS * 128)  // 110592

__global__ __launch_bounds__(ATHREADS, 2)
void attn_mma_kernel(const float* __restrict__ pe2,
                     const __half* __restrict__ QKVhi,
                     __half* __restrict__ Ohi)
{
    extern __shared__ __align__(128) char smem[];
    const uint32_t sb = smem_to_u32(smem);
    const int tid  = threadIdx.x;
    const int lane = tid & 31;
    const int wid  = tid >> 5;
    const int q0   = blockIdx.x * QROWS;
    const int bh   = blockIdx.y;
    const int b    = bh >> 4;
    const int h    = bh & 15;

    const size_t rowbase = (size_t)b * SEQ;

    // Stage loader: 128 keys (2048 x 16B chunks across 2 planes)
    auto load_kv = [&](int kj) {
        const int k0 = kj * 128;
        const uint32_t stg = sb + (uint32_t)((kj % 3) * KV_STAGE);
        for (int c = tid; c < 2048; c += ATHREADS) {
            const int plane = c >> 10;          // 0 Khi 1 Vhi
            const int idx = c & 1023;
            const int row = idx >> 3, ch = idx & 7;
            int kr = k0 + row;
            if (kr >= SEQ) kr = SEQ - 1;        // clamp; masked via S later
            const int coloff = (plane == 0) ? DIMN : 2 * DIMN;
            cp16(stg + plane * KV_PLANE + sw128(row, ch),
                 QKVhi + (rowbase + kr) * PLD + coloff + h * HD + ch * 8);
        }
    };

    {
        const size_t gq = (rowbase + q0) * PLD + h * HD;
        for (int c = tid; c < QROWS * 8; c += ATHREADS) {
            const int row = c >> 3, ch = c & 7;
            cp16(sb + Q_OFF + sw128(row, ch), QKVhi + gq + (size_t)row * PLD + ch * 8);
        }
    }
    load_kv(0); CP_COMMIT();
    load_kv(1); CP_COMMIT();

    const int Rq   = wid * 16 + (lane & 15);
    const int xorQ = Rq & 7;
    const int cqa  = lane >> 4;
    const uint32_t qBase = sb + Q_OFF + (uint32_t)(Rq * 128);
    const int Rk   = ((lane >> 4) << 3) + (lane & 7);
    const int xorK = lane & 7;
    const int ckb  = (lane >> 3) & 1;
    const int Rv   = lane & 15;
    const int xorV = lane & 7;
    const int cvb  = lane >> 4;

    const int r0  = lane >> 2;
    const int c2  = (lane & 3) * 2;
    const int qr  = q0 + wid * 16 + r0;
    const float* peA = pe2 + (size_t)qr * SEQ;
    const float* peB = pe2 + (size_t)(qr + 8) * SEQ;

    float o[8][4];
#pragma unroll
    for (int i = 0; i < 8; i++)
#pragma unroll
        for (int c = 0; c < 4; c++) o[i][c] = 0.f;
    float mrow0 = -INFINITY, mrow1 = -INFINITY;
    float lsum0 = 0.f, lsum1 = 0.f;

    for (int kj = 0; kj < 4; kj++) {
        CP_WAIT1();
        __syncthreads();                 // stage kj ready; buf (kj+2)%3 free

        if (kj + 2 < 4) load_kv(kj + 2);
        CP_COMMIT();

        const uint32_t stg = sb + (uint32_t)((kj % 3) * KV_STAGE);

#pragma unroll
        for (int sub = 0; sub < 2; sub++) {
            const uint32_t kvK = stg + (uint32_t)(sub * 8192);
            const uint32_t kvV = stg + KV_PLANE + (uint32_t)(sub * 8192);
            const int k0 = kj * 128 + sub * 64;

            // ---- S = Qh @ Kh^T ----
            float s[8][4];
#pragma unroll
            for (int i = 0; i < 8; i++)
#pragma unroll
                for (int c = 0; c < 4; c++) s[i][c] = 0.f;

#pragma unroll
            for (int ks = 0; ks < 4; ks++) {
                uint32_t qh[4];
                ldsm_x4(qh, qBase + (uint32_t)((((cqa + 2 * ks) ^ xorQ)) << 4));
                uint32_t kh[4][4];
#pragma unroll
                for (int ng = 0; ng < 4; ng++)
                    ldsm_x4(kh[ng], kvK + (uint32_t)((Rk + ng * 16) * 128) +
                                    (uint32_t)((((ckb + 2 * ks) ^ xorK)) << 4));
#pragma unroll
                for (int ni = 0; ni < 8; ni++)
                    mma16816(s[ni], qh, &kh[ni >> 1][(ni & 1) * 2]);
            }

            // ---- scale (log2 domain) + pe bias + mask ----
#pragma unroll
            for (int ni = 0; ni < 8; ni++) {
                const int kc = k0 + ni * 8 + c2;
                if (kc < SEQ) {
                    float2 pA = *(const float2*)(peA + kc);
                    float2 pB = *(const float2*)(peB + kc);
                    s[ni][0] = s[ni][0] * SCALE_LOG2E + pA.x;
                    s[ni][1] = s[ni][1] * SCALE_LOG2E + pA.y;
                    s[ni][2] = s[ni][2] * SCALE_LOG2E + pB.x;
                    s[ni][3] = s[ni][3] * SCALE_LOG2E + pB.y;
                } else {
                    s[ni][0] = -1e30f; s[ni][1] = -1e30f;
                    s[ni][2] = -1e30f; s[ni][3] = -1e30f;
                }
            }

            // ---- online softmax (base-2) ----
            float m0 = -INFINITY, m1 = -INFINITY;
#pragma unroll
            for (int ni = 0; ni < 8; ni++) {
                m0 = fmaxf(m0, fmaxf(s[ni][0], s[ni][1]));
                m1 = fmaxf(m1, fmaxf(s[ni][2], s[ni][3]));
            }
            m0 = fmaxf(m0, __shfl_xor_sync(0xffffffffu, m0, 1));
            m0 = fmaxf(m0, __shfl_xor_sync(0xffffffffu, m0, 2));
            m1 = fmaxf(m1, __shfl_xor_sync(0xffffffffu, m1, 1));
            m1 = fmaxf(m1, __shfl_xor_sync(0xffffffffu, m1, 2));

            const float mn0 = fmaxf(mrow0, m0);
            const float mn1 = fmaxf(mrow1, m1);
            const float f0 = exp2f(mrow0 - mn0);
            const float f1 = exp2f(mrow1 - mn1);
            mrow0 = mn0; mrow1 = mn1;

            float sum0 = 0.f, sum1 = 0.f;
            uint32_t phi[4][4];
#pragma unroll
            for (int ks = 0; ks < 4; ks++) {
                const int n0i = 2 * ks, n1i = 2 * ks + 1;
                float p00 = exp2f(s[n0i][0] - mn0), p01 = exp2f(s[n0i][1] - mn0);
                float p02 = exp2f(s[n0i][2] - mn1), p03 = exp2f(s[n0i][3] - mn1);
                float p10 = exp2f(s[n1i][0] - mn0), p11 = exp2f(s[n1i][1] - mn0);
                float p12 = exp2f(s[n1i][2] - mn1), p13 = exp2f(s[n1i][3] - mn1);
                sum0 += p00 + p01 + p10 + p11;
                sum1 += p02 + p03 + p12 + p13;
                phi[ks][0] = pack_h2(p00, p01);
                phi[ks][1] = pack_h2(p02, p03);
                phi[ks][2] = pack_h2(p10, p11);
                phi[ks][3] = pack_h2(p12, p13);
            }
            lsum0 = lsum0 * f0 + sum0;
            lsum1 = lsum1 * f1 + sum1;

#pragma unroll
            for (int ni = 0; ni < 8; ni++) {
                o[ni][0] *= f0; o[ni][1] *= f0;
                o[ni][2] *= f1; o[ni][3] *= f1;
            }

            // ---- O += Ph @ Vh ----
#pragma unroll
            for (int ks = 0; ks < 4; ks++) {
                uint32_t vh[4][4];
#pragma unroll
                for (int dg = 0; dg < 4; dg++)
                    ldsm_x4_t(vh[dg], kvV + (uint32_t)((Rv + ks * 16) * 128) +
                                      (uint32_t)((((cvb + 2 * dg) ^ xorV)) << 4));
#pragma unroll
                for (int ni = 0; ni < 8; ni++)
                    mma16816(o[ni], phi[ks], &vh[ni >> 1][(ni & 1) * 2]);
            }
        }
    }

    lsum0 += __shfl_xor_sync(0xffffffffu, lsum0, 1);
    lsum0 += __shfl_xor_sync(0xffffffffu, lsum0, 2);
    lsum1 += __shfl_xor_sync(0xffffffffu, lsum1, 1);
    lsum1 += __shfl_xor_sync(0xffffffffu, lsum1, 2);
    const float inv0 = 1.f / lsum0;
    const float inv1 = 1.f / lsum1;

    const size_t orow0 = (rowbase + qr) * DIMN + h * HD;
    const size_t orow1 = (rowbase + qr + 8) * DIMN + h * HD;
#pragma unroll
    for (int ni = 0; ni < 8; ni++) {
        const int d = ni * 8 + c2;
        *(__half2*)(Ohi + orow0 + d) =
            __half2{__float2half_rn(o[ni][0] * inv0), __float2half_rn(o[ni][1] * inv0)};
        *(__half2*)(Ohi + orow1 + d) =
            __half2{__float2half_rn(o[ni][2] * inv1), __float2half_rn(o[ni][3] * inv1)};
    }
}

// ---------------------------------------------------------------------------
extern "C" void kernel_launch(void* const* d_in, const int* in_sizes, int n_in,
                              void* d_out, int out_size)
{
    const float* q  = (const float*)d_in[0];
    const float* Wq = (const float*)d_in[1];
    const float* Wk = (const float*)d_in[2];
    const float* Wv = (const float*)d_in[3];
    const float* pe = (const float*)d_in[4];
    const float* Wo = (const float*)d_in[5];
    const float* bo = (const float*)d_in[6];
    float* out = (float*)d_out;

    __half *QKVhi, *qhi, *Ohi, *Wch, *Woh;
    float* pe2;
    cudaGetSymbolAddress((void**)&QKVhi, g_QKVhi);
    cudaGetSymbolAddress((void**)&qhi, g_qhi);
    cudaGetSymbolAddress((void**)&Ohi, g_Ohi);
    cudaGetSymbolAddress((void**)&Wch, g_Wcat_hi);
    cudaGetSymbolAddress((void**)&Woh, g_Wo_hi);
    cudaGetSymbolAddress((void**)&pe2, g_pe2);

    const int nw = DIMN * DIMN;

    // One launch: q tohalf + Wq/Wk/Wv/Wo tohalf + pe*log2e
    prep_kernel<<<PREP_TOTAL, 256>>>(q, Wq, Wk, Wv, Wo, pe,
                                     qhi, Wch, Wch + nw, Wch + 2 * nw, Woh, pe2);

    cudaFuncSetAttribute(gemm_f16x1<false, true>,
                         cudaFuncAttributeMaxDynamicSharedMemorySize, GEMM_SMEM);
    cudaFuncSetAttribute(gemm_f16x1<true, false>,
                         cudaFuncAttributeMaxDynamicSharedMemorySize, GEMM_SMEM);
    cudaFuncSetAttribute(attn_mma_kernel,
                         cudaFuncAttributeMaxDynamicSharedMemorySize, ATTN_SMEM);

    // Fused QKV projection -> fp16 hi [15360, 3072]
    gemm_f16x1<false, true><<<dim3(PLD / 128, MROWS / 128), GTHREADS, GEMM_SMEM>>>(
        qhi, Wch, nullptr, nullptr, QKVhi, PLD);

    // Tensor-core flash attention -> fp16 hi O
    attn_mma_kernel<<<dim3(SEQ / QROWS, BATCH * HEADS), ATHREADS, ATTN_SMEM>>>(
        pe2, QKVhi, Ohi);

    // Output projection + bias -> fp32 out
    gemm_f16x1<true, false><<<dim3(DIMN / 128, MROWS / 128), GTHREADS, GEMM_SMEM>>>(
        Ohi, Woh, bo, out, nullptr, DIMN);
}